// round 9
// baseline (speedup 1.0000x reference)
#include <cuda_runtime.h>
#include <cuda_bf16.h>

// Problem constants
#define B_TOT   32768
#define NPER    960        // 120*4*2
#define P1N     240
#define P2N     80
#define NLATENT 100

// Output layout (float elements):
//   z[B,100] | aug_xm[B,960] | aug_x_sd[B,1] | pool1_idx[B,240] | pool2_idx[B,80]
#define OFF_Z   ((size_t)0)
#define OFF_AXM ((size_t)B_TOT * NLATENT)
#define OFF_ASD (OFF_AXM + (size_t)B_TOT * NPER)
#define OFF_P1  (OFF_ASD + (size_t)B_TOT)
#define OFF_P2  (OFF_P1  + (size_t)B_TOT * P1N)

typedef unsigned long long u64;

// All prepped parameters live in __device__ globals (written by prep_kernel
// every call -> graph has exactly 2 kernel nodes, zero memcpy nodes).
__device__ u64   g_w1p[21];      // packed {w,w} conv1 weights
__device__ u64   g_w2p[21];      // packed {w,w} conv2 weights
__device__ u64   g_bb[2];        // packed {b,b} conv biases
__device__ float g_fm1X[800];    // [i<10][tid<80] = fcm1_w[(tid>>3)*80 + (tid&7) + 8i]
__device__ float g_fcX[1100];    // [k<11][t<100]  = fc_w[t*11 + k]

static __device__ __forceinline__ u64 pk2(float x, float y) {
    u64 r; asm("mov.b64 %0, {%1, %2};" : "=l"(r) : "f"(x), "f"(y)); return r;
}
static __device__ __forceinline__ void upk2(u64 v, float& x, float& y) {
    asm("mov.b64 {%0, %1}, %2;" : "=f"(x), "=f"(y) : "l"(v));
}
static __device__ __forceinline__ u64 ffma2(u64 a, u64 b, u64 c) {
    u64 d; asm("fma.rn.f32x2 %0, %1, %2, %3;" : "=l"(d) : "l"(a), "l"(b), "l"(c));
    return d;
}
// XOR swizzle on 16B-group index: spreads depth-strided accesses over bank groups
static __device__ __forceinline__ int SWZ(int g) { return g ^ ((g >> 3) & 7); }

__global__ void prep_kernel(const float* __restrict__ w1, const float* __restrict__ b1,
                            const float* __restrict__ w2, const float* __restrict__ b2,
                            const float* __restrict__ fcm1_w,
                            const float* __restrict__ fc_w) {
    const int t = threadIdx.x;
    if (t < 21) {
        float a = w1[t]; g_w1p[t] = pk2(a, a);
        float c = w2[t]; g_w2p[t] = pk2(c, c);
    }
    if (t == 32) { float v = b1[0]; g_bb[0] = pk2(v, v); }
    if (t == 33) { float v = b2[0]; g_bb[1] = pk2(v, v); }
    for (int idx = t; idx < 800; idx += 128) {
        int i = idx / 80, r = idx - i * 80;
        int j = r >> 3, s = r & 7;
        g_fm1X[idx] = fcm1_w[j * 80 + s + 8 * i];
    }
    for (int idx = t; idx < 1100; idx += 128) {
        int k = idx / 100, j = idx - k * 100;
        g_fcX[idx] = fc_w[j * 11 + k];
    }
}

__global__ __launch_bounds__(128, 6)
void enc_kernel(const float* __restrict__ x1, const float* __restrict__ x2,
                const float* __restrict__ fcm1_b, const float* __restrict__ fc_b,
                float* __restrict__ out)
{
    // Rows of 8 floats (= 2 float4 groups), depth-halo of 3 zero rows each side.
    __shared__ float4 xsh4[256];   // 126 rows (d+3 in 0..125) -> groups 0..251 (+swizzle pad)
    __shared__ float4 p1sh4[72];   // 36 rows  (d+3 in 0..35)  -> groups 0..71
    __shared__ float  p2v[P2N];
    __shared__ float  vec[11];     // [0..9]=ELU(fcm1), [10]=sigmoid(x2)

    const int tid = threadIdx.x;
    const int b   = blockIdx.x;

    // ---------------- Phase A: input staging + fused aug copies ----------------
    if (tid < 12) {      // zero depth-halo rows (groups 0..5 and 246..251)
        int g = (tid < 6) ? tid : (240 + tid);
        xsh4[SWZ(g)] = make_float4(0.f, 0.f, 0.f, 0.f);
        p1sh4[SWZ((tid < 6) ? tid : (60 + tid))] = make_float4(0.f, 0.f, 0.f, 0.f);
    }
    const float4* xin = (const float4*)(x1 + (size_t)b * NPER);
    float4*       axm = (float4*)(out + OFF_AXM + (size_t)b * NPER);
    {
        float4 v = xin[tid];
        axm[tid] = v;                           // aug_xm = x1 (eval identity)
        xsh4[SWZ(tid + 6)] = v;                 // group g = i + 6
    }
    if (tid < 112) {
        int i = tid + 128;
        float4 v = xin[i];
        axm[i] = v;
        xsh4[SWZ(i + 6)] = v;
    }
    if (tid == 120) {
        float xv = x2[b];
        out[OFF_ASD + b] = xv;                  // aug_x_sd = x2
        vec[10] = 1.0f / (1.0f + expf(-xv));
    }
    __syncthreads();

    // ------- Phase B: conv1(7,3,1)+ReLU+maxpool4+argmax -------
    // thread (dp, hp): dp in 0..29 pool group, hp selects h-pair {2hp, 2hp+1}
    if (tid < 60) {
        u64 w[21];
        #pragma unroll
        for (int i = 0; i < 21; i++) w[i] = g_w1p[i];   // uniform LDG -> broadcast, reg-resident
        const int dp = tid >> 1, hp = tid & 1;
        const bool hs = (hp != 0);
        u64 acc[4][2];
        {
            u64 bi = g_bb[0];
            #pragma unroll
            for (int j = 0; j < 4; j++) { acc[j][0] = bi; acc[j][1] = bi; }
        }
        #pragma unroll
        for (int kd = 0; kd < 10; kd++) {
            const int r = 4 * dp + kd;                // halo row index
            ulonglong2 A  = *(const ulonglong2*)&xsh4[SWZ(2 * r)];      // u64 pairs direct
            ulonglong2 Bv = *(const ulonglong2*)&xsh4[SWZ(2 * r + 1)];
            // W[m] = h-position (2hp-1+m); zero arms double as h-boundary padding
            u64 W0 = hs ? A.y  : 0ULL;
            u64 W1 = hs ? Bv.x : A.x;
            u64 W2 = hs ? Bv.y : A.y;
            u64 W3 = hs ? 0ULL : Bv.x;
            #pragma unroll
            for (int j = 0; j < 4; j++) {
                const int a = kd - j;
                if (a < 0 || a > 6) continue;
                acc[j][0] = ffma2(W0, w[a * 3 + 0], acc[j][0]);
                acc[j][0] = ffma2(W1, w[a * 3 + 1], acc[j][0]);
                acc[j][0] = ffma2(W2, w[a * 3 + 2], acc[j][0]);
                acc[j][1] = ffma2(W1, w[a * 3 + 0], acc[j][1]);
                acc[j][1] = ffma2(W2, w[a * 3 + 1], acc[j][1]);
                acc[j][1] = ffma2(W3, w[a * 3 + 2], acc[j][1]);
            }
        }
        float bv0 = -1.f, bv1 = -1.f, bv2 = -1.f, bv3 = -1.f;
        int   bi0 = 0, bi1 = 0, bi2 = 0, bi3 = 0;
        #pragma unroll
        for (int j = 0; j < 4; j++) {
            float p00, p01, p10, p11, v;
            upk2(acc[j][0], p00, p01); upk2(acc[j][1], p10, p11);
            v = fmaxf(p00, 0.f); if (v > bv0) { bv0 = v; bi0 = j; }  // strict > = first-max
            v = fmaxf(p01, 0.f); if (v > bv1) { bv1 = v; bi1 = j; }
            v = fmaxf(p10, 0.f); if (v > bv2) { bv2 = v; bi2 = j; }
            v = fmaxf(p11, 0.f); if (v > bv3) { bv3 = v; bi3 = j; }
        }
        p1sh4[SWZ(2 * (dp + 3) + hp)] = make_float4(bv0, bv1, bv2, bv3);
        const int h0 = 2 * hp, d0 = 4 * dp;
        float4 iv;
        iv.x = (float)(((d0 + bi0) * 4 + h0) * 2 + 0);
        iv.y = (float)(((d0 + bi1) * 4 + h0) * 2 + 1);
        iv.z = (float)(((d0 + bi2) * 4 + h0 + 1) * 2 + 0);
        iv.w = (float)(((d0 + bi3) * 4 + h0 + 1) * 2 + 1);
        *(float4*)&out[OFF_P1 + (size_t)b * P1N + dp * 8 + hp * 4] = iv;
    }
    __syncthreads();

    // ------- Phase C: conv2(7,3,1)+ReLU+maxpool3+argmax -------
    if (tid < 20) {
        u64 w[21];
        #pragma unroll
        for (int i = 0; i < 21; i++) w[i] = g_w2p[i];
        const int dp = tid >> 1, hp = tid & 1;
        const bool hs = (hp != 0);
        u64 acc[3][2];
        {
            u64 bi = g_bb[1];
            #pragma unroll
            for (int j = 0; j < 3; j++) { acc[j][0] = bi; acc[j][1] = bi; }
        }
        #pragma unroll
        for (int t = 0; t < 9; t++) {
            const int r = 3 * dp + t;
            ulonglong2 A  = *(const ulonglong2*)&p1sh4[SWZ(2 * r)];
            ulonglong2 Bv = *(const ulonglong2*)&p1sh4[SWZ(2 * r + 1)];
            u64 W0 = hs ? A.y  : 0ULL;
            u64 W1 = hs ? Bv.x : A.x;
            u64 W2 = hs ? Bv.y : A.y;
            u64 W3 = hs ? 0ULL : Bv.x;
            #pragma unroll
            for (int j = 0; j < 3; j++) {
                const int a = t - j;
                if (a < 0 || a > 6) continue;
                acc[j][0] = ffma2(W0, w[a * 3 + 0], acc[j][0]);
                acc[j][0] = ffma2(W1, w[a * 3 + 1], acc[j][0]);
                acc[j][0] = ffma2(W2, w[a * 3 + 2], acc[j][0]);
                acc[j][1] = ffma2(W1, w[a * 3 + 0], acc[j][1]);
                acc[j][1] = ffma2(W2, w[a * 3 + 1], acc[j][1]);
                acc[j][1] = ffma2(W3, w[a * 3 + 2], acc[j][1]);
            }
        }
        float bv0 = -1.f, bv1 = -1.f, bv2 = -1.f, bv3 = -1.f;
        int   bi0 = 0, bi1 = 0, bi2 = 0, bi3 = 0;
        #pragma unroll
        for (int j = 0; j < 3; j++) {
            float p00, p01, p10, p11, v;
            upk2(acc[j][0], p00, p01); upk2(acc[j][1], p10, p11);
            v = fmaxf(p00, 0.f); if (v > bv0) { bv0 = v; bi0 = j; }
            v = fmaxf(p01, 0.f); if (v > bv1) { bv1 = v; bi1 = j; }
            v = fmaxf(p10, 0.f); if (v > bv2) { bv2 = v; bi2 = j; }
            v = fmaxf(p11, 0.f); if (v > bv3) { bv3 = v; bi3 = j; }
        }
        *(float4*)&p2v[dp * 8 + hp * 4] = make_float4(bv0, bv1, bv2, bv3);
        const int h0 = 2 * hp, d0 = 3 * dp;
        float4 iv;
        iv.x = (float)(((d0 + bi0) * 4 + h0) * 2 + 0);
        iv.y = (float)(((d0 + bi1) * 4 + h0) * 2 + 1);
        iv.z = (float)(((d0 + bi2) * 4 + h0 + 1) * 2 + 0);
        iv.w = (float)(((d0 + bi3) * 4 + h0 + 1) * 2 + 1);
        *(float4*)&out[OFF_P2 + (size_t)b * P2N + dp * 8 + hp * 4] = iv;
    }
    __syncthreads();

    // ------- Phase E: fcm1 (80->10) + ELU, 8 lanes/output, coalesced weights -------
    if (tid < 80) {
        const int j = tid >> 3, s = tid & 7;
        float acc = 0.0f;
        #pragma unroll
        for (int i = 0; i < 10; i++)
            acc = fmaf(p2v[s + 8 * i], g_fm1X[80 * i + tid], acc);   // 128B/warp-instr
        unsigned m = __activemask();
        acc += __shfl_xor_sync(m, acc, 4);
        acc += __shfl_xor_sync(m, acc, 2);
        acc += __shfl_xor_sync(m, acc, 1);
        if (s == 0) {
            float t = acc + fcm1_b[j];
            vec[j] = (t > 0.0f) ? t : expm1f(t);
        }
    }
    __syncthreads();

    // ------- Phase F: fc (11->100) + BatchNorm eval -------
    if (tid < NLATENT) {
        float acc = fc_b[tid];
        #pragma unroll
        for (int k = 0; k < 11; k++)
            acc = fmaf(vec[k], g_fcX[k * 100 + tid], acc);           // coalesced
        out[OFF_Z + (size_t)b * NLATENT + tid] = acc * 0.9999950000374996f;
    }
}

extern "C" void kernel_launch(void* const* d_in, const int* in_sizes, int n_in,
                              void* d_out, int out_size)
{
    const float* x1     = (const float*)d_in[0];
    const float* x2     = (const float*)d_in[1];
    // d_in[2]=shifts, d_in[3]=nonzero_mask_xm : unused in eval-mode forward
    const float* w1     = (const float*)d_in[4];
    const float* b1     = (const float*)d_in[5];
    const float* w2     = (const float*)d_in[6];
    const float* b2     = (const float*)d_in[7];
    const float* fcm1_w = (const float*)d_in[8];
    const float* fcm1_b = (const float*)d_in[9];
    const float* fc_w   = (const float*)d_in[10];
    const float* fc_b   = (const float*)d_in[11];
    float* out = (float*)d_out;

    prep_kernel<<<1, 128>>>(w1, b1, w2, b2, fcm1_w, fc_w);
    enc_kernel<<<B_TOT, 128>>>(x1, x2, fcm1_b, fc_b, out);
}

// round 10
// speedup vs baseline: 1.3074x; 1.3074x over previous
#include <cuda_runtime.h>
#include <cuda_bf16.h>

// Problem constants
#define B_TOT   32768
#define NPER    960        // 120*4*2
#define P1N     240
#define P2N     80
#define NLATENT 100

// Output layout (float elements):
//   z[B,100] | aug_xm[B,960] | aug_x_sd[B,1] | pool1_idx[B,240] | pool2_idx[B,80]
#define OFF_Z   ((size_t)0)
#define OFF_AXM ((size_t)B_TOT * NLATENT)
#define OFF_ASD (OFF_AXM + (size_t)B_TOT * NPER)
#define OFF_P1  (OFF_ASD + (size_t)B_TOT)
#define OFF_P2  (OFF_P1  + (size_t)B_TOT * P1N)

typedef unsigned long long u64;

// Consolidated constant bank: packed {w,w} conv weights + {b,b} biases.
struct __align__(16) CParams {
    u64 w1p[21];
    u64 w2p[21];
    u64 bb[2];
};
__constant__ CParams c_p;

// Staging buffer written by prep_kernel, copied to c_p by ONE memcpy node.
__device__ u64   g_stage[44];
// Pre-swizzled GEMV weights (read via coalesced LDG in enc)
__device__ float g_fm1X[800];    // [i<10][tid<80] = fcm1_w[(tid>>3)*80 + (tid&7) + 8i]
__device__ float g_fcX[1100];    // [k<11][t<100]  = fc_w[t*11 + k]

static __device__ __forceinline__ u64 pk2(float x, float y) {
    u64 r; asm("mov.b64 %0, {%1, %2};" : "=l"(r) : "f"(x), "f"(y)); return r;
}
static __device__ __forceinline__ void upk2(u64 v, float& x, float& y) {
    asm("mov.b64 {%0, %1}, %2;" : "=f"(x), "=f"(y) : "l"(v));
}
static __device__ __forceinline__ u64 ffma2(u64 a, u64 b, u64 c) {
    u64 d; asm("fma.rn.f32x2 %0, %1, %2, %3;" : "=l"(d) : "l"(a), "l"(b), "l"(c));
    return d;
}
// XOR swizzle on 16B-group index: spreads depth-strided accesses over bank groups
static __device__ __forceinline__ int SWZ(int g) { return g ^ ((g >> 3) & 7); }

__global__ void prep_kernel(const float* __restrict__ w1, const float* __restrict__ b1,
                            const float* __restrict__ w2, const float* __restrict__ b2,
                            const float* __restrict__ fcm1_w,
                            const float* __restrict__ fc_w) {
    const int t = threadIdx.x;
    if (t < 21) {
        float a = w1[t]; g_stage[t]      = pk2(a, a);
        float c = w2[t]; g_stage[21 + t] = pk2(c, c);
    }
    if (t == 32) { float v = b1[0]; g_stage[42] = pk2(v, v); }
    if (t == 33) { float v = b2[0]; g_stage[43] = pk2(v, v); }
    for (int idx = t; idx < 800; idx += 128) {
        int i = idx / 80, r = idx - i * 80;
        int j = r >> 3, s = r & 7;
        g_fm1X[idx] = fcm1_w[j * 80 + s + 8 * i];
    }
    for (int idx = t; idx < 1100; idx += 128) {
        int k = idx / 100, j = idx - k * 100;
        g_fcX[idx] = fc_w[j * 11 + k];
    }
}

__global__ __launch_bounds__(128, 6)
void enc_kernel(const float* __restrict__ x1, const float* __restrict__ x2,
                const float* __restrict__ fcm1_b, const float* __restrict__ fc_b,
                float* __restrict__ out)
{
    // Rows of 8 floats (= 2 float4 groups), depth-halo of 3 zero rows each side.
    __shared__ float4 xsh4[256];   // 126 rows (d+3 in 0..125) -> groups 0..251 (+swizzle pad)
    __shared__ float4 p1sh4[72];   // 36 rows  (d+3 in 0..35)  -> groups 0..71
    __shared__ float  p2v[P2N];
    __shared__ float  vec[11];     // [0..9]=ELU(fcm1), [10]=sigmoid(x2)

    const int tid = threadIdx.x;
    const int b   = blockIdx.x;

    // ---------------- Phase A: input staging + fused aug copies ----------------
    if (tid < 12) {      // zero depth-halo rows (groups 0..5 and 246..251)
        int g = (tid < 6) ? tid : (240 + tid);
        xsh4[SWZ(g)] = make_float4(0.f, 0.f, 0.f, 0.f);
        p1sh4[SWZ((tid < 6) ? tid : (60 + tid))] = make_float4(0.f, 0.f, 0.f, 0.f);
    }
    const float4* xin = (const float4*)(x1 + (size_t)b * NPER);
    float4*       axm = (float4*)(out + OFF_AXM + (size_t)b * NPER);
    {
        float4 v = xin[tid];
        axm[tid] = v;                           // aug_xm = x1 (eval identity)
        xsh4[SWZ(tid + 6)] = v;                 // group g = i + 6
    }
    if (tid < 112) {
        int i = tid + 128;
        float4 v = xin[i];
        axm[i] = v;
        xsh4[SWZ(i + 6)] = v;
    }
    if (tid == 120) {
        float xv = x2[b];
        out[OFF_ASD + b] = xv;                  // aug_x_sd = x2
        vec[10] = 1.0f / (1.0f + expf(-xv));
    }
    __syncthreads();

    // ------- Phase B: conv1(7,3,1)+ReLU+maxpool4+argmax -------
    // thread (dp, hp): dp in 0..29 pool group, hp selects h-pair {2hp, 2hp+1}
    if (tid < 60) {
        const int dp = tid >> 1, hp = tid & 1;
        const bool hs = (hp != 0);
        u64 acc[4][2];
        {
            u64 bi = c_p.bb[0];
            #pragma unroll
            for (int j = 0; j < 4; j++) { acc[j][0] = bi; acc[j][1] = bi; }
        }
        #pragma unroll
        for (int kd = 0; kd < 10; kd++) {
            const int r = 4 * dp + kd;                // halo row index
            ulonglong2 A  = *(const ulonglong2*)&xsh4[SWZ(2 * r)];      // u64 pairs direct
            ulonglong2 Bv = *(const ulonglong2*)&xsh4[SWZ(2 * r + 1)];
            // W[m] = h-position (2hp-1+m); zero arms double as h-boundary padding
            u64 W0 = hs ? A.y  : 0ULL;
            u64 W1 = hs ? Bv.x : A.x;
            u64 W2 = hs ? Bv.y : A.y;
            u64 W3 = hs ? 0ULL : Bv.x;
            #pragma unroll
            for (int j = 0; j < 4; j++) {
                const int a = kd - j;
                if (a < 0 || a > 6) continue;
                acc[j][0] = ffma2(W0, c_p.w1p[a * 3 + 0], acc[j][0]);
                acc[j][0] = ffma2(W1, c_p.w1p[a * 3 + 1], acc[j][0]);
                acc[j][0] = ffma2(W2, c_p.w1p[a * 3 + 2], acc[j][0]);
                acc[j][1] = ffma2(W1, c_p.w1p[a * 3 + 0], acc[j][1]);
                acc[j][1] = ffma2(W2, c_p.w1p[a * 3 + 1], acc[j][1]);
                acc[j][1] = ffma2(W3, c_p.w1p[a * 3 + 2], acc[j][1]);
            }
        }
        float bv0 = -1.f, bv1 = -1.f, bv2 = -1.f, bv3 = -1.f;
        int   bi0 = 0, bi1 = 0, bi2 = 0, bi3 = 0;
        #pragma unroll
        for (int j = 0; j < 4; j++) {
            float p00, p01, p10, p11, v;
            upk2(acc[j][0], p00, p01); upk2(acc[j][1], p10, p11);
            v = fmaxf(p00, 0.f); if (v > bv0) { bv0 = v; bi0 = j; }  // strict > = first-max
            v = fmaxf(p01, 0.f); if (v > bv1) { bv1 = v; bi1 = j; }
            v = fmaxf(p10, 0.f); if (v > bv2) { bv2 = v; bi2 = j; }
            v = fmaxf(p11, 0.f); if (v > bv3) { bv3 = v; bi3 = j; }
        }
        p1sh4[SWZ(2 * (dp + 3) + hp)] = make_float4(bv0, bv1, bv2, bv3);
        const int h0 = 2 * hp, d0 = 4 * dp;
        float4 iv;
        iv.x = (float)(((d0 + bi0) * 4 + h0) * 2 + 0);
        iv.y = (float)(((d0 + bi1) * 4 + h0) * 2 + 1);
        iv.z = (float)(((d0 + bi2) * 4 + h0 + 1) * 2 + 0);
        iv.w = (float)(((d0 + bi3) * 4 + h0 + 1) * 2 + 1);
        *(float4*)&out[OFF_P1 + (size_t)b * P1N + dp * 8 + hp * 4] = iv;
    }
    __syncthreads();

    // ------- Phase C: conv2(7,3,1)+ReLU+maxpool3+argmax -------
    if (tid < 20) {
        const int dp = tid >> 1, hp = tid & 1;
        const bool hs = (hp != 0);
        u64 acc[3][2];
        {
            u64 bi = c_p.bb[1];
            #pragma unroll
            for (int j = 0; j < 3; j++) { acc[j][0] = bi; acc[j][1] = bi; }
        }
        #pragma unroll
        for (int t = 0; t < 9; t++) {
            const int r = 3 * dp + t;
            ulonglong2 A  = *(const ulonglong2*)&p1sh4[SWZ(2 * r)];
            ulonglong2 Bv = *(const ulonglong2*)&p1sh4[SWZ(2 * r + 1)];
            u64 W0 = hs ? A.y  : 0ULL;
            u64 W1 = hs ? Bv.x : A.x;
            u64 W2 = hs ? Bv.y : A.y;
            u64 W3 = hs ? 0ULL : Bv.x;
            #pragma unroll
            for (int j = 0; j < 3; j++) {
                const int a = t - j;
                if (a < 0 || a > 6) continue;
                acc[j][0] = ffma2(W0, c_p.w2p[a * 3 + 0], acc[j][0]);
                acc[j][0] = ffma2(W1, c_p.w2p[a * 3 + 1], acc[j][0]);
                acc[j][0] = ffma2(W2, c_p.w2p[a * 3 + 2], acc[j][0]);
                acc[j][1] = ffma2(W1, c_p.w2p[a * 3 + 0], acc[j][1]);
                acc[j][1] = ffma2(W2, c_p.w2p[a * 3 + 1], acc[j][1]);
                acc[j][1] = ffma2(W3, c_p.w2p[a * 3 + 2], acc[j][1]);
            }
        }
        float bv0 = -1.f, bv1 = -1.f, bv2 = -1.f, bv3 = -1.f;
        int   bi0 = 0, bi1 = 0, bi2 = 0, bi3 = 0;
        #pragma unroll
        for (int j = 0; j < 3; j++) {
            float p00, p01, p10, p11, v;
            upk2(acc[j][0], p00, p01); upk2(acc[j][1], p10, p11);
            v = fmaxf(p00, 0.f); if (v > bv0) { bv0 = v; bi0 = j; }
            v = fmaxf(p01, 0.f); if (v > bv1) { bv1 = v; bi1 = j; }
            v = fmaxf(p10, 0.f); if (v > bv2) { bv2 = v; bi2 = j; }
            v = fmaxf(p11, 0.f); if (v > bv3) { bv3 = v; bi3 = j; }
        }
        *(float4*)&p2v[dp * 8 + hp * 4] = make_float4(bv0, bv1, bv2, bv3);
        const int h0 = 2 * hp, d0 = 3 * dp;
        float4 iv;
        iv.x = (float)(((d0 + bi0) * 4 + h0) * 2 + 0);
        iv.y = (float)(((d0 + bi1) * 4 + h0) * 2 + 1);
        iv.z = (float)(((d0 + bi2) * 4 + h0 + 1) * 2 + 0);
        iv.w = (float)(((d0 + bi3) * 4 + h0 + 1) * 2 + 1);
        *(float4*)&out[OFF_P2 + (size_t)b * P2N + dp * 8 + hp * 4] = iv;
    }
    __syncthreads();

    // ------- Phase E: fcm1 (80->10) + ELU, 8 lanes/output, coalesced weights -------
    if (tid < 80) {
        const int j = tid >> 3, s = tid & 7;
        float acc = 0.0f;
        #pragma unroll
        for (int i = 0; i < 10; i++)
            acc = fmaf(p2v[s + 8 * i], g_fm1X[80 * i + tid], acc);   // 128B/warp-instr
        unsigned m = __activemask();
        acc += __shfl_xor_sync(m, acc, 4);
        acc += __shfl_xor_sync(m, acc, 2);
        acc += __shfl_xor_sync(m, acc, 1);
        if (s == 0) {
            float t = acc + fcm1_b[j];
            vec[j] = (t > 0.0f) ? t : expm1f(t);
        }
    }
    __syncthreads();

    // ------- Phase F: fc (11->100) + BatchNorm eval -------
    if (tid < NLATENT) {
        float acc = fc_b[tid];
        #pragma unroll
        for (int k = 0; k < 11; k++)
            acc = fmaf(vec[k], g_fcX[k * 100 + tid], acc);           // coalesced
        out[OFF_Z + (size_t)b * NLATENT + tid] = acc * 0.9999950000374996f;
    }
}

extern "C" void kernel_launch(void* const* d_in, const int* in_sizes, int n_in,
                              void* d_out, int out_size)
{
    const float* x1     = (const float*)d_in[0];
    const float* x2     = (const float*)d_in[1];
    // d_in[2]=shifts, d_in[3]=nonzero_mask_xm : unused in eval-mode forward
    const float* w1     = (const float*)d_in[4];
    const float* b1     = (const float*)d_in[5];
    const float* w2     = (const float*)d_in[6];
    const float* b2     = (const float*)d_in[7];
    const float* fcm1_w = (const float*)d_in[8];
    const float* fcm1_b = (const float*)d_in[9];
    const float* fc_w   = (const float*)d_in[10];
    const float* fc_b   = (const float*)d_in[11];
    float* out = (float*)d_out;

    prep_kernel<<<1, 128>>>(w1, b1, w2, b2, fcm1_w, fc_w);

    // ONE consolidated D2D memcpy node: staging -> constant bank
    void* stage_ptr = nullptr;
    cudaGetSymbolAddress(&stage_ptr, g_stage);        // host-side lookup, no alloc
    cudaMemcpyToSymbolAsync(c_p, stage_ptr, sizeof(CParams), 0,
                            cudaMemcpyDeviceToDevice, 0);

    enc_kernel<<<B_TOT, 128>>>(x1, x2, fcm1_b, fc_b, out);
}

// round 11
// speedup vs baseline: 1.3435x; 1.0277x over previous
#include <cuda_runtime.h>
#include <cuda_bf16.h>

// Problem constants
#define B_TOT   32768
#define NPER    960        // 120*4*2
#define P1N     240
#define P2N     80
#define NLATENT 100

// Output layout (float elements):
//   z[B,100] | aug_xm[B,960] | aug_x_sd[B,1] | pool1_idx[B,240] | pool2_idx[B,80]
#define OFF_Z   ((size_t)0)
#define OFF_AXM ((size_t)B_TOT * NLATENT)
#define OFF_ASD (OFF_AXM + (size_t)B_TOT * NPER)
#define OFF_P1  (OFF_ASD + (size_t)B_TOT)
#define OFF_P2  (OFF_P1  + (size_t)B_TOT * P1N)

typedef unsigned long long u64;

// Consolidated constant bank: packed {w,w} conv weights + {b,b} biases.
struct __align__(16) CParams {
    u64 w1p[21];
    u64 w2p[21];
    u64 bb[2];
};
__constant__ CParams c_p;

// Staging buffer written by prep_kernel, copied to c_p by ONE memcpy node.
__device__ u64   g_stage[44];
// Pre-swizzled GEMV weights (read via coalesced LDG in enc)
__device__ float g_fm1X[800];    // [i<10][tid<80] = fcm1_w[(tid>>3)*80 + (tid&7) + 8i]
__device__ float g_fcX[1100];    // [k<11][t<100]  = fc_w[t*11 + k]

static __device__ __forceinline__ u64 pk2(float x, float y) {
    u64 r; asm("mov.b64 %0, {%1, %2};" : "=l"(r) : "f"(x), "f"(y)); return r;
}
static __device__ __forceinline__ void upk2(u64 v, float& x, float& y) {
    asm("mov.b64 {%0, %1}, %2;" : "=f"(x), "=f"(y) : "l"(v));
}
static __device__ __forceinline__ u64 ffma2(u64 a, u64 b, u64 c) {
    u64 d; asm("fma.rn.f32x2 %0, %1, %2, %3;" : "=l"(d) : "l"(a), "l"(b), "l"(c));
    return d;
}
// XOR swizzle on 16B-group index: spreads depth-strided accesses over bank groups
static __device__ __forceinline__ int SWZ(int g) { return g ^ ((g >> 3) & 7); }

__global__ void prep_kernel(const float* __restrict__ w1, const float* __restrict__ b1,
                            const float* __restrict__ w2, const float* __restrict__ b2,
                            const float* __restrict__ fcm1_w,
                            const float* __restrict__ fc_w) {
    const int t = threadIdx.x;
    if (t < 21) {
        float a = w1[t]; g_stage[t]      = pk2(a, a);
        float c = w2[t]; g_stage[21 + t] = pk2(c, c);
    }
    if (t == 32) { float v = b1[0]; g_stage[42] = pk2(v, v); }
    if (t == 33) { float v = b2[0]; g_stage[43] = pk2(v, v); }
    for (int idx = t; idx < 800; idx += 128) {
        int i = idx / 80, r = idx - i * 80;
        int j = r >> 3, s = r & 7;
        g_fm1X[idx] = fcm1_w[j * 80 + s + 8 * i];
    }
    for (int idx = t; idx < 1100; idx += 128) {
        int k = idx / 100, j = idx - k * 100;
        g_fcX[idx] = fc_w[j * 11 + k];
    }
}

__global__ __launch_bounds__(128, 6)
void enc_kernel(const float* __restrict__ x1, const float* __restrict__ x2,
                const float* __restrict__ fcm1_b, const float* __restrict__ fc_b,
                float* __restrict__ out)
{
    // Rows of 8 floats (= 2 float4 groups), depth-halo of 3 zero rows each side.
    // Row r: group 2r = {h0w0,h0w1,h1w0,h1w1}, group 2r+1 = {h2w0,h2w1,h3w0,h3w1}.
    __shared__ float4 xsh4[256];   // 126 rows (d+3 in 0..125) -> groups 0..251 (+swizzle pad)
    __shared__ float4 p1sh4[72];   // 36 rows  (d+3 in 0..35)  -> groups 0..71
    __shared__ float  p2v[P2N];
    __shared__ float  vec[11];     // [0..9]=ELU(fcm1), [10]=sigmoid(x2)

    const int tid = threadIdx.x;
    const int b   = blockIdx.x;

    // ---------------- Phase A: input staging + fused aug copies ----------------
    if (tid < 12) {      // zero depth-halo rows (groups 0..5 and 246..251)
        int g = (tid < 6) ? tid : (240 + tid);
        xsh4[SWZ(g)] = make_float4(0.f, 0.f, 0.f, 0.f);
        p1sh4[SWZ((tid < 6) ? tid : (60 + tid))] = make_float4(0.f, 0.f, 0.f, 0.f);
    }
    const float4* xin = (const float4*)(x1 + (size_t)b * NPER);
    float4*       axm = (float4*)(out + OFF_AXM + (size_t)b * NPER);
    {
        float4 v = xin[tid];
        axm[tid] = v;                           // aug_xm = x1 (eval identity)
        xsh4[SWZ(tid + 6)] = v;                 // group g = i + 6
    }
    if (tid < 112) {
        int i = tid + 128;
        float4 v = xin[i];
        axm[i] = v;
        xsh4[SWZ(i + 6)] = v;
    }
    if (tid == 120) {
        float xv = x2[b];
        out[OFF_ASD + b] = xv;                  // aug_x_sd = x2
        vec[10] = 1.0f / (1.0f + expf(-xv));
    }
    __syncthreads();

    // ------- Phase B: conv1(7,3,1)+ReLU+maxpool4+argmax, hp warp-specialized -------
    // warp0: hp=0 (outputs h=0,1); warp1: hp=1 (outputs h=2,3); dp = lane (0..29)
    if (tid < 64) {
        const int hp = tid >> 5;
        const int dp = tid & 31;
        if (dp < 30) {
            u64 acc[4][2];
            {
                u64 bi = c_p.bb[0];
                #pragma unroll
                for (int j = 0; j < 4; j++) { acc[j][0] = bi; acc[j][1] = bi; }
            }
            if (hp == 0) {        // warp-uniform branch, no divergence
                #pragma unroll
                for (int kd = 0; kd < 10; kd++) {
                    const int r = 4 * dp + kd;
                    ulonglong2 A = *(const ulonglong2*)&xsh4[SWZ(2 * r)];       // h0,h1
                    u64        Bx = *(const u64*)&xsh4[SWZ(2 * r + 1)];         // h2
                    #pragma unroll
                    for (int j = 0; j < 4; j++) {
                        const int a = kd - j;
                        if (a < 0 || a > 6) continue;
                        // out h=0: taps in[-1](zero, skipped), in[0], in[1]
                        acc[j][0] = ffma2(A.x, c_p.w1p[a * 3 + 1], acc[j][0]);
                        acc[j][0] = ffma2(A.y, c_p.w1p[a * 3 + 2], acc[j][0]);
                        // out h=1: taps in[0], in[1], in[2]
                        acc[j][1] = ffma2(A.x, c_p.w1p[a * 3 + 0], acc[j][1]);
                        acc[j][1] = ffma2(A.y, c_p.w1p[a * 3 + 1], acc[j][1]);
                        acc[j][1] = ffma2(Bx,  c_p.w1p[a * 3 + 2], acc[j][1]);
                    }
                }
            } else {
                #pragma unroll
                for (int kd = 0; kd < 10; kd++) {
                    const int r = 4 * dp + kd;
                    u64        Ay = ((const u64*)&xsh4[SWZ(2 * r)])[1];          // h1
                    ulonglong2 Bv = *(const ulonglong2*)&xsh4[SWZ(2 * r + 1)];   // h2,h3
                    #pragma unroll
                    for (int j = 0; j < 4; j++) {
                        const int a = kd - j;
                        if (a < 0 || a > 6) continue;
                        // out h=2: taps in[1], in[2], in[3]
                        acc[j][0] = ffma2(Ay,   c_p.w1p[a * 3 + 0], acc[j][0]);
                        acc[j][0] = ffma2(Bv.x, c_p.w1p[a * 3 + 1], acc[j][0]);
                        acc[j][0] = ffma2(Bv.y, c_p.w1p[a * 3 + 2], acc[j][0]);
                        // out h=3: taps in[2], in[3], in[4](zero, skipped)
                        acc[j][1] = ffma2(Bv.x, c_p.w1p[a * 3 + 0], acc[j][1]);
                        acc[j][1] = ffma2(Bv.y, c_p.w1p[a * 3 + 1], acc[j][1]);
                    }
                }
            }
            float bv0 = -1.f, bv1 = -1.f, bv2 = -1.f, bv3 = -1.f;
            int   bi0 = 0, bi1 = 0, bi2 = 0, bi3 = 0;
            #pragma unroll
            for (int j = 0; j < 4; j++) {
                float p00, p01, p10, p11, v;
                upk2(acc[j][0], p00, p01); upk2(acc[j][1], p10, p11);
                v = fmaxf(p00, 0.f); if (v > bv0) { bv0 = v; bi0 = j; }  // strict > = first-max
                v = fmaxf(p01, 0.f); if (v > bv1) { bv1 = v; bi1 = j; }
                v = fmaxf(p10, 0.f); if (v > bv2) { bv2 = v; bi2 = j; }
                v = fmaxf(p11, 0.f); if (v > bv3) { bv3 = v; bi3 = j; }
            }
            p1sh4[SWZ(2 * (dp + 3) + hp)] = make_float4(bv0, bv1, bv2, bv3);
            const int h0 = 2 * hp, d0 = 4 * dp;
            float4 iv;
            iv.x = (float)(((d0 + bi0) * 4 + h0) * 2 + 0);
            iv.y = (float)(((d0 + bi1) * 4 + h0) * 2 + 1);
            iv.z = (float)(((d0 + bi2) * 4 + h0 + 1) * 2 + 0);
            iv.w = (float)(((d0 + bi3) * 4 + h0 + 1) * 2 + 1);
            *(float4*)&out[OFF_P1 + (size_t)b * P1N + dp * 8 + hp * 4] = iv;
        }
    }
    __syncthreads();

    // ------- Phase C: conv2(7,3,1)+ReLU+maxpool3+argmax, hp warp-specialized -------
    if (tid < 64) {
        const int hp = tid >> 5;
        const int dp = tid & 31;
        if (dp < 10) {
            u64 acc[3][2];
            {
                u64 bi = c_p.bb[1];
                #pragma unroll
                for (int j = 0; j < 3; j++) { acc[j][0] = bi; acc[j][1] = bi; }
            }
            if (hp == 0) {
                #pragma unroll
                for (int t = 0; t < 9; t++) {
                    const int r = 3 * dp + t;
                    ulonglong2 A = *(const ulonglong2*)&p1sh4[SWZ(2 * r)];
                    u64        Bx = *(const u64*)&p1sh4[SWZ(2 * r + 1)];
                    #pragma unroll
                    for (int j = 0; j < 3; j++) {
                        const int a = t - j;
                        if (a < 0 || a > 6) continue;
                        acc[j][0] = ffma2(A.x, c_p.w2p[a * 3 + 1], acc[j][0]);
                        acc[j][0] = ffma2(A.y, c_p.w2p[a * 3 + 2], acc[j][0]);
                        acc[j][1] = ffma2(A.x, c_p.w2p[a * 3 + 0], acc[j][1]);
                        acc[j][1] = ffma2(A.y, c_p.w2p[a * 3 + 1], acc[j][1]);
                        acc[j][1] = ffma2(Bx,  c_p.w2p[a * 3 + 2], acc[j][1]);
                    }
                }
            } else {
                #pragma unroll
                for (int t = 0; t < 9; t++) {
                    const int r = 3 * dp + t;
                    u64        Ay = ((const u64*)&p1sh4[SWZ(2 * r)])[1];
                    ulonglong2 Bv = *(const ulonglong2*)&p1sh4[SWZ(2 * r + 1)];
                    #pragma unroll
                    for (int j = 0; j < 3; j++) {
                        const int a = t - j;
                        if (a < 0 || a > 6) continue;
                        acc[j][0] = ffma2(Ay,   c_p.w2p[a * 3 + 0], acc[j][0]);
                        acc[j][0] = ffma2(Bv.x, c_p.w2p[a * 3 + 1], acc[j][0]);
                        acc[j][0] = ffma2(Bv.y, c_p.w2p[a * 3 + 2], acc[j][0]);
                        acc[j][1] = ffma2(Bv.x, c_p.w2p[a * 3 + 0], acc[j][1]);
                        acc[j][1] = ffma2(Bv.y, c_p.w2p[a * 3 + 1], acc[j][1]);
                    }
                }
            }
            float bv0 = -1.f, bv1 = -1.f, bv2 = -1.f, bv3 = -1.f;
            int   bi0 = 0, bi1 = 0, bi2 = 0, bi3 = 0;
            #pragma unroll
            for (int j = 0; j < 3; j++) {
                float p00, p01, p10, p11, v;
                upk2(acc[j][0], p00, p01); upk2(acc[j][1], p10, p11);
                v = fmaxf(p00, 0.f); if (v > bv0) { bv0 = v; bi0 = j; }
                v = fmaxf(p01, 0.f); if (v > bv1) { bv1 = v; bi1 = j; }
                v = fmaxf(p10, 0.f); if (v > bv2) { bv2 = v; bi2 = j; }
                v = fmaxf(p11, 0.f); if (v > bv3) { bv3 = v; bi3 = j; }
            }
            *(float4*)&p2v[dp * 8 + hp * 4] = make_float4(bv0, bv1, bv2, bv3);
            const int h0 = 2 * hp, d0 = 3 * dp;
            float4 iv;
            iv.x = (float)(((d0 + bi0) * 4 + h0) * 2 + 0);
            iv.y = (float)(((d0 + bi1) * 4 + h0) * 2 + 1);
            iv.z = (float)(((d0 + bi2) * 4 + h0 + 1) * 2 + 0);
            iv.w = (float)(((d0 + bi3) * 4 + h0 + 1) * 2 + 1);
            *(float4*)&out[OFF_P2 + (size_t)b * P2N + dp * 8 + hp * 4] = iv;
        }
    }
    __syncthreads();

    // ------- Phase E: fcm1 (80->10) + ELU, 8 lanes/output, coalesced weights -------
    if (tid < 80) {
        const int j = tid >> 3, s = tid & 7;
        float acc = 0.0f;
        #pragma unroll
        for (int i = 0; i < 10; i++)
            acc = fmaf(p2v[s + 8 * i], g_fm1X[80 * i + tid], acc);   // 128B/warp-instr
        unsigned m = __activemask();
        acc += __shfl_xor_sync(m, acc, 4);
        acc += __shfl_xor_sync(m, acc, 2);
        acc += __shfl_xor_sync(m, acc, 1);
        if (s == 0) {
            float t = acc + fcm1_b[j];
            vec[j] = (t > 0.0f) ? t : expm1f(t);
        }
    }
    __syncthreads();

    // ------- Phase F: fc (11->100) + BatchNorm eval -------
    if (tid < NLATENT) {
        float acc = fc_b[tid];
        #pragma unroll
        for (int k = 0; k < 11; k++)
            acc = fmaf(vec[k], g_fcX[k * 100 + tid], acc);           // coalesced
        out[OFF_Z + (size_t)b * NLATENT + tid] = acc * 0.9999950000374996f;
    }
}

extern "C" void kernel_launch(void* const* d_in, const int* in_sizes, int n_in,
                              void* d_out, int out_size)
{
    const float* x1     = (const float*)d_in[0];
    const float* x2     = (const float*)d_in[1];
    // d_in[2]=shifts, d_in[3]=nonzero_mask_xm : unused in eval-mode forward
    const float* w1     = (const float*)d_in[4];
    const float* b1     = (const float*)d_in[5];
    const float* w2     = (const float*)d_in[6];
    const float* b2     = (const float*)d_in[7];
    const float* fcm1_w = (const float*)d_in[8];
    const float* fcm1_b = (const float*)d_in[9];
    const float* fc_w   = (const float*)d_in[10];
    const float* fc_b   = (const float*)d_in[11];
    float* out = (float*)d_out;

    prep_kernel<<<1, 128>>>(w1, b1, w2, b2, fcm1_w, fc_w);

    // ONE consolidated D2D memcpy node: staging -> constant bank
    void* stage_ptr = nullptr;
    cudaGetSymbolAddress(&stage_ptr, g_stage);        // host-side lookup, no alloc
    cudaMemcpyToSymbolAsync(c_p, stage_ptr, sizeof(CParams), 0,
                            cudaMemcpyDeviceToDevice, 0);

    enc_kernel<<<B_TOT, 128>>>(x1, x2, fcm1_b, fc_b, out);
}